// round 10
// baseline (speedup 1.0000x reference)
#include <cuda_runtime.h>
#include <cuda_fp16.h>
#include <cuda_bf16.h>
#include <math.h>

#define NN 20000
#define BB 128
#define KK 20
#define EE 640000
#define NB (NN * BB)          // floats per T_k plane
#define CAP 96                // padded slots per row; deinterleaved by edge parity
#define HCAP 48               // slots per parity region
#define NCHUNK 1250
#define CHUNK 16
#define RCH 25                // stage-1 reduce: 25 CTAs x 50 chunks

// -------- static device scratch (no runtime allocation allowed) ----------
__device__ float g_T[(size_t)KK * NN * BB];     // fp32 masters (recursion + epilogue)
__device__ uint2 g_Th[(size_t)KK * NN * 32];    // fp16 planes, one per k (gather only)
__device__ int   g_cnt[NN];
// deinterleaved: row base + (p&1)*HCAP + (p>>1)  for logical slot p
__device__ int2  g_pack[(size_t)NN * CAP];
__device__ float g_partial[(size_t)NCHUNK * BB * 10];
__device__ float g_partial2[(size_t)RCH * BB * 10];

// ---------------------- packed f32x2 helpers -----------------------------
__device__ __forceinline__ unsigned long long dupf(float v) {
    unsigned long long d; unsigned u = __float_as_uint(v);
    asm("mov.b64 %0, {%1,%2};" : "=l"(d) : "r"(u), "r"(u));
    return d;
}
__device__ __forceinline__ unsigned long long h2f2(unsigned h) {
    __half2 hh = *reinterpret_cast<__half2*>(&h);
    float2 f = __half22float2(hh);
    unsigned long long d;
    asm("mov.b64 %0, {%1,%2};" : "=l"(d)
        : "r"(__float_as_uint(f.x)), "r"(__float_as_uint(f.y)));
    return d;
}
__device__ __forceinline__ void fma2(unsigned long long& a,
                                     unsigned long long v, unsigned long long p) {
    asm("fma.rn.f32x2 %0, %1, %2, %3;" : "=l"(a) : "l"(v), "l"(p), "l"(a));
}
__device__ __forceinline__ float2 unp(unsigned long long d) {
    unsigned lo, hi;
    asm("mov.b64 {%0,%1}, %2;" : "=r"(lo), "=r"(hi) : "l"(d));
    float2 f; f.x = __uint_as_float(lo); f.y = __uint_as_float(hi);
    return f;
}
__device__ __forceinline__ void hacc2(uint4 r, unsigned long long vv,
                                      unsigned long long* a) {
    fma2(a[0], vv, h2f2(r.x));
    fma2(a[1], vv, h2f2(r.y));
    fma2(a[2], vv, h2f2(r.z));
    fma2(a[3], vv, h2f2(r.w));
}

// ------ T0 = x^T + fp16 copy + zero cnt (runs first, alone) --------------
__global__ void transpose_zero_kernel(const float* __restrict__ x) {
    int gt = blockIdx.y * gridDim.x * 1024 + blockIdx.x * 1024 +
             threadIdx.y * 32 + threadIdx.x;
    int gsz = gridDim.x * gridDim.y * 1024;
    for (int i = gt; i < NN; i += gsz) g_cnt[i] = 0;

    __shared__ float tile[32][33];
    int n0 = blockIdx.x * 32, b0 = blockIdx.y * 32;
    int tn = n0 + threadIdx.x;
    int tb = b0 + threadIdx.y;          // always < 128
    if (tn < NN) tile[threadIdx.y][threadIdx.x] = x[(size_t)tb * NN + tn];
    __syncthreads();
    int on = n0 + threadIdx.y;
    int ob = b0 + threadIdx.x;
    if (on < NN) {
        float f = tile[threadIdx.x][threadIdx.y];
        g_T[(size_t)on * BB + ob] = f;
        __half* th = (__half*)g_Th;     // fp16 plane 0
        th[(size_t)on * BB + ob] = __float2half(f);
    }
}

// ---------------- padded CSR build (parity-deinterleaved) ----------------
__global__ void scatter_pad_kernel(const int* __restrict__ rows,
                                   const int* __restrict__ cols,
                                   const float* __restrict__ vals) {
    int e = blockIdx.x * blockDim.x + threadIdx.x;
    if (e < EE) {
        int r = rows[e];
        int p = atomicAdd(&g_cnt[r], 1);
        if (p < CAP) {
            int phys = (p & 1) * HCAP + (p >> 1);
            int2 pk;
            pk.x = cols[e];
            pk.y = __float_as_int(vals[e]);
            g_pack[(size_t)r * CAP + phys] = pk;
        }
    }
}

// zero only the tail slots [cnt, roundup16(cnt)) — replaces the 15.4MB wipe
__global__ void pad_kernel() {
    int w = (blockIdx.x * blockDim.x + threadIdx.x) >> 5;
    int lane = threadIdx.x & 31;
    if (w >= NN) return;
    int cnt = g_cnt[w];
    if (cnt > CAP) cnt = CAP;
    int e16 = (cnt + 15) & ~15;        // <= 96
    int p = cnt + lane;
    if (p < e16) {
        int phys = (p & 1) * HCAP + (p >> 1);
        int2 z; z.x = 0; z.y = 0;
        g_pack[(size_t)w * CAP + phys] = z;
    }
}

// -------------------- fused Chebyshev SpMM step --------------------------
// warp per row; half-warp g handles edges of parity g. Pack int4 broadcast
// loads fetch 2 own-parity edges. Dual f32x2 accumulator banks cut the FMA
// dependency chain 4x and the FMA issue count 2x.
__global__ void __launch_bounds__(256) spmm_kernel(int kin2, int kout,
                                                   float alpha, float beta) {
    int row = (blockIdx.x * blockDim.x + threadIdx.x) >> 5;   // grid covers NN exactly
    int lane = threadIdx.x & 31;
    int g = lane >> 4;          // half-warp group: edge parity
    int hl = lane & 15;         // covers 16B of the 256B fp16 row

    const uint4* __restrict__ Th =
        (const uint4*)(g_Th + (size_t)(kout - 1) * NN * 32);
    const int4* __restrict__ pk4 =
        (const int4*)(g_pack + (size_t)row * CAP) + g * (HCAP / 2);

    int cnt = g_cnt[row];
    if (cnt > CAP) cnt = CAP;
    int e16 = (cnt + 15) & ~15;   // zero-val padded tail -> branch-free

    unsigned long long accA[4], accB[4];
#pragma unroll
    for (int i = 0; i < 4; i++) { accA[i] = 0ull; accB[i] = 0ull; }

    for (int j = 0; j < e16; j += 16) {
        // own-parity edges j+g, j+2+g, ..., j+14+g : 4 int4 broadcast loads
        int4 Q0 = pk4[(j >> 2) + 0];
        int4 Q1 = pk4[(j >> 2) + 1];
        int4 Q2 = pk4[(j >> 2) + 2];
        int4 Q3 = pk4[(j >> 2) + 3];
        uint4 r0 = Th[(size_t)Q0.x * 16 + hl];
        uint4 r1 = Th[(size_t)Q0.z * 16 + hl];
        uint4 r2 = Th[(size_t)Q1.x * 16 + hl];
        uint4 r3 = Th[(size_t)Q1.z * 16 + hl];
        uint4 r4 = Th[(size_t)Q2.x * 16 + hl];
        uint4 r5 = Th[(size_t)Q2.z * 16 + hl];
        uint4 r6 = Th[(size_t)Q3.x * 16 + hl];
        uint4 r7 = Th[(size_t)Q3.z * 16 + hl];
        hacc2(r0, dupf(__int_as_float(Q0.y)), accA);
        hacc2(r1, dupf(__int_as_float(Q0.w)), accB);
        hacc2(r2, dupf(__int_as_float(Q1.y)), accA);
        hacc2(r3, dupf(__int_as_float(Q1.w)), accB);
        hacc2(r4, dupf(__int_as_float(Q2.y)), accA);
        hacc2(r5, dupf(__int_as_float(Q2.w)), accB);
        hacc2(r6, dupf(__int_as_float(Q3.y)), accA);
        hacc2(r7, dupf(__int_as_float(Q3.w)), accB);
    }

    float f[8];
#pragma unroll
    for (int i = 0; i < 4; i++) {
        float2 a = unp(accA[i]);
        float2 b = unp(accB[i]);
        f[2 * i]     = a.x + b.x;
        f[2 * i + 1] = a.y + b.y;
    }

    // combine the two half-warp edge streams (same batch range)
#pragma unroll
    for (int i = 0; i < 8; i++) f[i] += __shfl_xor_sync(0xffffffffu, f[i], 16);

    float o[8];
    size_t ob = (size_t)row * 32 + (size_t)hl * 2;
    if (beta != 0.f) {
        const float4* __restrict__ Tp = (const float4*)(g_T + (size_t)kin2 * NB);
        float4 p0 = Tp[ob], p1 = Tp[ob + 1];
        o[0] = fmaf(alpha, f[0], beta * p0.x);
        o[1] = fmaf(alpha, f[1], beta * p0.y);
        o[2] = fmaf(alpha, f[2], beta * p0.z);
        o[3] = fmaf(alpha, f[3], beta * p0.w);
        o[4] = fmaf(alpha, f[4], beta * p1.x);
        o[5] = fmaf(alpha, f[5], beta * p1.y);
        o[6] = fmaf(alpha, f[6], beta * p1.z);
        o[7] = fmaf(alpha, f[7], beta * p1.w);
    } else {
#pragma unroll
        for (int i = 0; i < 8; i++) o[i] = f[i];   // alpha == 1 for T1
    }

    if (g == 0) {
        // lanes 0-15: fp32 master writeback (2x STG.128)
        float4* __restrict__ Tout = (float4*)(g_T + (size_t)kout * NB);
        Tout[ob]     = make_float4(o[0], o[1], o[2], o[3]);
        Tout[ob + 1] = make_float4(o[4], o[5], o[6], o[7]);
    } else {
        // lanes 16-31: fp16 plane writeback (1x STG.128)
        uint4* __restrict__ ThO = (uint4*)(g_Th + (size_t)kout * NN * 32);
        __half2 h0 = __floats2half2_rn(o[0], o[1]);
        __half2 h1 = __floats2half2_rn(o[2], o[3]);
        __half2 h2 = __floats2half2_rn(o[4], o[5]);
        __half2 h3 = __floats2half2_rn(o[6], o[7]);
        uint4 u;
        u.x = *reinterpret_cast<unsigned*>(&h0);
        u.y = *reinterpret_cast<unsigned*>(&h1);
        u.z = *reinterpret_cast<unsigned*>(&h2);
        u.w = *reinterpret_cast<unsigned*>(&h3);
        ThO[(size_t)row * 16 + hl] = u;
    }
}

// --------- fused epilogue: gc einsum + relu + FC partial sums ------------
// reads the fp32 masters (fp16 readout overflowed the 1e-3 budget in R8)
__global__ void __launch_bounds__(128) final_kernel(const float* __restrict__ Wgc,
                                                    const float* __restrict__ bgc,
                                                    const float* __restrict__ Wfc) {
    __shared__ float sW[KK * 12];   // padded to 12 floats/row for float4 LDS
    __shared__ float sb[10];
    int t = threadIdx.x;
    for (int i = t; i < KK * 12; i += 128) sW[i] = 0.f;
    __syncthreads();
    for (int i = t; i < KK * 10; i += 128) {
        int k = i / 10, fidx = i % 10;
        sW[k * 12 + fidx] = Wgc[i];
    }
    if (t < 10) sb[t] = bgc[t];
    __syncthreads();

    const float4* sW4 = (const float4*)sW;
    int b = t;

    float h[10];
#pragma unroll
    for (int j = 0; j < 10; j++) h[j] = 0.f;

    int n0 = blockIdx.x * CHUNK;
    for (int n = n0; n < n0 + CHUNK; n++) {
        float gc[10];
#pragma unroll
        for (int fidx = 0; fidx < 10; fidx++) gc[fidx] = sb[fidx];
#pragma unroll
        for (int k = 0; k < KK; k++) {
            float tk = g_T[(size_t)k * NB + (size_t)n * BB + b];
            float4 wA = sW4[k * 3 + 0];
            float4 wB = sW4[k * 3 + 1];
            float4 wC = sW4[k * 3 + 2];
            gc[0] += tk * wA.x; gc[1] += tk * wA.y; gc[2] += tk * wA.z; gc[3] += tk * wA.w;
            gc[4] += tk * wB.x; gc[5] += tk * wB.y; gc[6] += tk * wB.z; gc[7] += tk * wB.w;
            gc[8] += tk * wC.x; gc[9] += tk * wC.y;
        }
#pragma unroll
        for (int fidx = 0; fidx < 10; fidx++) gc[fidx] = fmaxf(gc[fidx], 0.f);

        const float4* __restrict__ w4 = (const float4*)(Wfc + (size_t)n * 100);
#pragma unroll
        for (int q = 0; q < 25; q++) {
            float4 wv = w4[q];
            h[(4 * q + 0) % 10] += gc[(4 * q + 0) / 10] * wv.x;
            h[(4 * q + 1) % 10] += gc[(4 * q + 1) / 10] * wv.y;
            h[(4 * q + 2) % 10] += gc[(4 * q + 2) / 10] * wv.z;
            h[(4 * q + 3) % 10] += gc[(4 * q + 3) / 10] * wv.w;
        }
    }

    float* out = g_partial + (size_t)blockIdx.x * BB * 10 + (size_t)b * 10;
#pragma unroll
    for (int j = 0; j < 10; j++) out[j] = h[j];
}

// ----------------- two-stage deterministic reduction ---------------------
__global__ void reduce1_kernel() {
    int b = threadIdx.x;   // 128
    int c0 = blockIdx.x * (NCHUNK / RCH);         // 50 chunks per CTA
    float h[10];
#pragma unroll
    for (int j = 0; j < 10; j++) h[j] = 0.f;
    for (int c = c0; c < c0 + NCHUNK / RCH; c++) {
        const float* p = g_partial + (size_t)c * BB * 10 + (size_t)b * 10;
#pragma unroll
        for (int j = 0; j < 10; j++) h[j] += p[j];
    }
    float* out = g_partial2 + (size_t)blockIdx.x * BB * 10 + (size_t)b * 10;
#pragma unroll
    for (int j = 0; j < 10; j++) out[j] = h[j];
}

__global__ void reduce_softmax_kernel(const float* __restrict__ bfc,
                                      float* __restrict__ out) {
    int b = threadIdx.x;   // 128 threads
    float h[10];
#pragma unroll
    for (int j = 0; j < 10; j++) h[j] = 0.f;
    for (int c = 0; c < RCH; c++) {
        const float* p = g_partial2 + (size_t)c * BB * 10 + (size_t)b * 10;
#pragma unroll
        for (int j = 0; j < 10; j++) h[j] += p[j];
    }
#pragma unroll
    for (int j = 0; j < 10; j++) h[j] = fmaxf(h[j] + bfc[j], 0.f);
    float m = h[0];
#pragma unroll
    for (int j = 1; j < 10; j++) m = fmaxf(m, h[j]);
    float ex[10];
    float s = 0.f;
#pragma unroll
    for (int j = 0; j < 10; j++) { ex[j] = expf(h[j] - m); s += ex[j]; }
    float inv = 1.f / s;
#pragma unroll
    for (int j = 0; j < 10; j++) out[(size_t)b * 10 + j] = ex[j] * inv;
}

// ------------------------------- launch ----------------------------------
extern "C" void kernel_launch(void* const* d_in, const int* in_sizes, int n_in,
                              void* d_out, int out_size) {
    const float* x    = (const float*)d_in[0];
    const int*   rows = (const int*)d_in[1];
    const int*   cols = (const int*)d_in[2];
    const float* vals = (const float*)d_in[3];
    const float* Wgc  = (const float*)d_in[4];
    const float* bgc  = (const float*)d_in[5];
    const float* Wfc  = (const float*)d_in[6];
    const float* bfc  = (const float*)d_in[7];
    float* out = (float*)d_out;

    dim3 tb(32, 32), tg((NN + 31) / 32, (BB + 31) / 32);
    transpose_zero_kernel<<<tg, tb>>>(x);
    scatter_pad_kernel<<<(EE + 255) / 256, 256>>>(rows, cols, vals);
    pad_kernel<<<(NN * 32 + 255) / 256, 256>>>();

    // Chebyshev chain: T1 = L T0 ; T_k = 2 L T_{k-1} - T_{k-2}
    const int SPMM_GRID = (NN * 32) / 256;   // warp per row, exact
    spmm_kernel<<<SPMM_GRID, 256>>>(0, 1, 1.0f, 0.0f);
    for (int k = 2; k < KK; k++)
        spmm_kernel<<<SPMM_GRID, 256>>>(k - 2, k, 2.0f, -1.0f);

    final_kernel<<<NCHUNK, 128>>>(Wgc, bgc, Wfc);
    reduce1_kernel<<<RCH, 128>>>();
    reduce_softmax_kernel<<<1, 128>>>(bfc, out);
}

// round 11
// speedup vs baseline: 1.0946x; 1.0946x over previous
#include <cuda_runtime.h>
#include <cuda_fp16.h>
#include <cuda_bf16.h>
#include <math.h>

#define NN 20000
#define BB 128
#define KK 20
#define EE 640000
#define NB (NN * BB)          // floats per T_k plane
#define CAP 96                // padded slots per row; deinterleaved by edge parity
#define HCAP 48               // slots per parity region
#define NCHUNK 1250
#define CHUNK 16
#define RCH 25                // stage-1 reduce: 25 CTAs x 50 chunks

#define NBLK 888              // 148 SMs x 6 co-resident CTAs (forced by launch_bounds)
#define NWARP (NBLK * 8)

// -------- static device scratch (no runtime allocation allowed) ----------
__device__ float g_T[(size_t)KK * NN * BB];     // fp32 masters (recursion + epilogue)
__device__ uint2 g_Th[(size_t)KK * NN * 32];    // fp16 planes, one per k (gather only)
__device__ int   g_cnt[NN];
// deinterleaved: row base + (p&1)*HCAP + (p>>1)  for logical slot p
__device__ int2  g_pack[(size_t)NN * CAP];
__device__ float g_partial[(size_t)NCHUNK * BB * 10];
__device__ float g_partial2[(size_t)RCH * BB * 10];

// software grid barrier state (monotonic phase survives graph replays)
__device__ int          g_bar = 0;
__device__ volatile int g_phase = 0;

// ------ T0 = x^T + fp16 copy + zero cnt (runs first, alone) --------------
__global__ void transpose_zero_kernel(const float* __restrict__ x) {
    int gt = blockIdx.y * gridDim.x * 1024 + blockIdx.x * 1024 +
             threadIdx.y * 32 + threadIdx.x;
    int gsz = gridDim.x * gridDim.y * 1024;
    for (int i = gt; i < NN; i += gsz) g_cnt[i] = 0;

    __shared__ float tile[32][33];
    int n0 = blockIdx.x * 32, b0 = blockIdx.y * 32;
    int tn = n0 + threadIdx.x;
    int tb = b0 + threadIdx.y;          // always < 128
    if (tn < NN) tile[threadIdx.y][threadIdx.x] = x[(size_t)tb * NN + tn];
    __syncthreads();
    int on = n0 + threadIdx.y;
    int ob = b0 + threadIdx.x;
    if (on < NN) {
        float f = tile[threadIdx.x][threadIdx.y];
        g_T[(size_t)on * BB + ob] = f;
        __half* th = (__half*)g_Th;     // fp16 plane 0
        th[(size_t)on * BB + ob] = __float2half(f);
    }
}

// ---------------- padded CSR build (parity-deinterleaved) ----------------
__global__ void scatter_pad_kernel(const int* __restrict__ rows,
                                   const int* __restrict__ cols,
                                   const float* __restrict__ vals) {
    int e = blockIdx.x * blockDim.x + threadIdx.x;
    if (e < EE) {
        int r = rows[e];
        int p = atomicAdd(&g_cnt[r], 1);
        if (p < CAP) {
            int phys = (p & 1) * HCAP + (p >> 1);
            int2 pk;
            pk.x = cols[e];
            pk.y = __float_as_int(vals[e]);
            g_pack[(size_t)r * CAP + phys] = pk;
        }
    }
}

// zero only the tail slots [cnt, roundup16(cnt)) — no 15.4MB wipe
__global__ void pad_kernel() {
    int w = (blockIdx.x * blockDim.x + threadIdx.x) >> 5;
    int lane = threadIdx.x & 31;
    if (w >= NN) return;
    int cnt = g_cnt[w];
    if (cnt > CAP) cnt = CAP;
    int e16 = (cnt + 15) & ~15;        // <= 96
    int p = cnt + lane;
    if (p < e16) {
        int phys = (p & 1) * HCAP + (p >> 1);
        int2 z; z.x = 0; z.y = 0;
        g_pack[(size_t)w * CAP + phys] = z;
    }
}

// ------------- persistent fused Chebyshev chain (19 steps) ---------------
// warp strides rows; half-warp g handles edges of parity g; scalar fp32
// accumulators (R9-proven: 32 regs, occ ~74%). Software grid barrier
// between steps replaces 18 kernel launches + grid drains.
__device__ __forceinline__ void hacc8(uint4 r, float v, float* f) {
    float2 fa = __half22float2(*reinterpret_cast<__half2*>(&r.x));
    float2 fb = __half22float2(*reinterpret_cast<__half2*>(&r.y));
    float2 fc = __half22float2(*reinterpret_cast<__half2*>(&r.z));
    float2 fd = __half22float2(*reinterpret_cast<__half2*>(&r.w));
    f[0] = fmaf(v, fa.x, f[0]); f[1] = fmaf(v, fa.y, f[1]);
    f[2] = fmaf(v, fb.x, f[2]); f[3] = fmaf(v, fb.y, f[3]);
    f[4] = fmaf(v, fc.x, f[4]); f[5] = fmaf(v, fc.y, f[5]);
    f[6] = fmaf(v, fd.x, f[6]); f[7] = fmaf(v, fd.y, f[7]);
}

__global__ void __launch_bounds__(256, 6) cheb_kernel() {
    int wid = threadIdx.x >> 5;
    int lane = threadIdx.x & 31;
    int gw0 = blockIdx.x * 8 + wid;
    int g = lane >> 4;          // half-warp group: edge parity
    int hl = lane & 15;         // covers 16B of the 256B fp16 row

    __shared__ int s_ph;
    if (threadIdx.x == 0) s_ph = g_phase;   // stable: no bump until all arrive
    __syncthreads();
    int ph = s_ph;

    for (int k = 1; k < KK; k++) {
        const uint4* __restrict__ Th =
            (const uint4*)(g_Th + (size_t)(k - 1) * NN * 32);
        const float alpha = (k == 1) ? 1.0f : 2.0f;
        const float beta  = (k == 1) ? 0.0f : -1.0f;

        for (int row = gw0; row < NN; row += NWARP) {
            const int4* __restrict__ pk4 =
                (const int4*)(g_pack + (size_t)row * CAP) + g * (HCAP / 2);
            int cnt = g_cnt[row];
            if (cnt > CAP) cnt = CAP;
            int e16 = (cnt + 15) & ~15;

            float f[8];
#pragma unroll
            for (int i = 0; i < 8; i++) f[i] = 0.f;

            for (int j = 0; j < e16; j += 16) {
                int4 Q0 = pk4[(j >> 2) + 0];
                int4 Q1 = pk4[(j >> 2) + 1];
                int4 Q2 = pk4[(j >> 2) + 2];
                int4 Q3 = pk4[(j >> 2) + 3];
                uint4 r0 = Th[(size_t)Q0.x * 16 + hl];
                uint4 r1 = Th[(size_t)Q0.z * 16 + hl];
                uint4 r2 = Th[(size_t)Q1.x * 16 + hl];
                uint4 r3 = Th[(size_t)Q1.z * 16 + hl];
                uint4 r4 = Th[(size_t)Q2.x * 16 + hl];
                uint4 r5 = Th[(size_t)Q2.z * 16 + hl];
                uint4 r6 = Th[(size_t)Q3.x * 16 + hl];
                uint4 r7 = Th[(size_t)Q3.z * 16 + hl];
                hacc8(r0, __int_as_float(Q0.y), f);
                hacc8(r1, __int_as_float(Q0.w), f);
                hacc8(r2, __int_as_float(Q1.y), f);
                hacc8(r3, __int_as_float(Q1.w), f);
                hacc8(r4, __int_as_float(Q2.y), f);
                hacc8(r5, __int_as_float(Q2.w), f);
                hacc8(r6, __int_as_float(Q3.y), f);
                hacc8(r7, __int_as_float(Q3.w), f);
            }

            // combine the two half-warp edge streams
#pragma unroll
            for (int i = 0; i < 8; i++)
                f[i] += __shfl_xor_sync(0xffffffffu, f[i], 16);

            float o[8];
            size_t ob = (size_t)row * 32 + (size_t)hl * 2;
            if (beta != 0.f) {
                const float4* __restrict__ Tp =
                    (const float4*)(g_T + (size_t)(k - 2) * NB);
                float4 p0 = Tp[ob], p1 = Tp[ob + 1];
                o[0] = fmaf(alpha, f[0], beta * p0.x);
                o[1] = fmaf(alpha, f[1], beta * p0.y);
                o[2] = fmaf(alpha, f[2], beta * p0.z);
                o[3] = fmaf(alpha, f[3], beta * p0.w);
                o[4] = fmaf(alpha, f[4], beta * p1.x);
                o[5] = fmaf(alpha, f[5], beta * p1.y);
                o[6] = fmaf(alpha, f[6], beta * p1.z);
                o[7] = fmaf(alpha, f[7], beta * p1.w);
            } else {
#pragma unroll
                for (int i = 0; i < 8; i++) o[i] = f[i];   // alpha == 1 for T1
            }

            if (g == 0) {
                float4* __restrict__ Tout = (float4*)(g_T + (size_t)k * NB);
                Tout[ob]     = make_float4(o[0], o[1], o[2], o[3]);
                Tout[ob + 1] = make_float4(o[4], o[5], o[6], o[7]);
            } else {
                uint4* __restrict__ ThO = (uint4*)(g_Th + (size_t)k * NN * 32);
                __half2 h0 = __floats2half2_rn(o[0], o[1]);
                __half2 h1 = __floats2half2_rn(o[2], o[3]);
                __half2 h2 = __floats2half2_rn(o[4], o[5]);
                __half2 h3 = __floats2half2_rn(o[6], o[7]);
                uint4 u;
                u.x = *reinterpret_cast<unsigned*>(&h0);
                u.y = *reinterpret_cast<unsigned*>(&h1);
                u.z = *reinterpret_cast<unsigned*>(&h2);
                u.w = *reinterpret_cast<unsigned*>(&h3);
                ThO[(size_t)row * 16 + hl] = u;
            }
        }

        // ---- grid barrier (release writes, arrive, spin, acquire) ----
        __syncthreads();
        if (threadIdx.x == 0) {
            __threadfence();                       // release my plane writes
            int t = atomicAdd(&g_bar, 1);
            if (t == NBLK - 1) {
                g_bar = 0;
                __threadfence();                   // order reset before phase bump
                g_phase = ph + k;
            } else {
                while (g_phase - (ph + k) < 0) __nanosleep(64);
            }
            __threadfence();                       // acquire others' writes
        }
        __syncthreads();
    }
}

// --------- fused epilogue: gc einsum + relu + FC partial sums ------------
__global__ void __launch_bounds__(128) final_kernel(const float* __restrict__ Wgc,
                                                    const float* __restrict__ bgc,
                                                    const float* __restrict__ Wfc) {
    __shared__ float sW[KK * 12];   // padded to 12 floats/row for float4 LDS
    __shared__ float sb[10];
    int t = threadIdx.x;
    for (int i = t; i < KK * 12; i += 128) sW[i] = 0.f;
    __syncthreads();
    for (int i = t; i < KK * 10; i += 128) {
        int k = i / 10, fidx = i % 10;
        sW[k * 12 + fidx] = Wgc[i];
    }
    if (t < 10) sb[t] = bgc[t];
    __syncthreads();

    const float4* sW4 = (const float4*)sW;
    int b = t;

    float h[10];
#pragma unroll
    for (int j = 0; j < 10; j++) h[j] = 0.f;

    int n0 = blockIdx.x * CHUNK;
    for (int n = n0; n < n0 + CHUNK; n++) {
        float gc[10];
#pragma unroll
        for (int fidx = 0; fidx < 10; fidx++) gc[fidx] = sb[fidx];
#pragma unroll
        for (int k = 0; k < KK; k++) {
            float tk = g_T[(size_t)k * NB + (size_t)n * BB + b];
            float4 wA = sW4[k * 3 + 0];
            float4 wB = sW4[k * 3 + 1];
            float4 wC = sW4[k * 3 + 2];
            gc[0] += tk * wA.x; gc[1] += tk * wA.y; gc[2] += tk * wA.z; gc[3] += tk * wA.w;
            gc[4] += tk * wB.x; gc[5] += tk * wB.y; gc[6] += tk * wB.z; gc[7] += tk * wB.w;
            gc[8] += tk * wC.x; gc[9] += tk * wC.y;
        }
#pragma unroll
        for (int fidx = 0; fidx < 10; fidx++) gc[fidx] = fmaxf(gc[fidx], 0.f);

        const float4* __restrict__ w4 = (const float4*)(Wfc + (size_t)n * 100);
#pragma unroll
        for (int q = 0; q < 25; q++) {
            float4 wv = w4[q];
            h[(4 * q + 0) % 10] += gc[(4 * q + 0) / 10] * wv.x;
            h[(4 * q + 1) % 10] += gc[(4 * q + 1) / 10] * wv.y;
            h[(4 * q + 2) % 10] += gc[(4 * q + 2) / 10] * wv.z;
            h[(4 * q + 3) % 10] += gc[(4 * q + 3) / 10] * wv.w;
        }
    }

    float* out = g_partial + (size_t)blockIdx.x * BB * 10 + (size_t)b * 10;
#pragma unroll
    for (int j = 0; j < 10; j++) out[j] = h[j];
}

// ----------------- two-stage deterministic reduction ---------------------
__global__ void reduce1_kernel() {
    int b = threadIdx.x;   // 128
    int c0 = blockIdx.x * (NCHUNK / RCH);         // 50 chunks per CTA
    float h[10];
#pragma unroll
    for (int j = 0; j < 10; j++) h[j] = 0.f;
    for (int c = c0; c < c0 + NCHUNK / RCH; c++) {
        const float* p = g_partial + (size_t)c * BB * 10 + (size_t)b * 10;
#pragma unroll
        for (int j = 0; j < 10; j++) h[j] += p[j];
    }
    float* out = g_partial2 + (size_t)blockIdx.x * BB * 10 + (size_t)b * 10;
#pragma unroll
    for (int j = 0; j < 10; j++) out[j] = h[j];
}

__global__ void reduce_softmax_kernel(const float* __restrict__ bfc,
                                      float* __restrict__ out) {
    int b = threadIdx.x;   // 128 threads
    float h[10];
#pragma unroll
    for (int j = 0; j < 10; j++) h[j] = 0.f;
    for (int c = 0; c < RCH; c++) {
        const float* p = g_partial2 + (size_t)c * BB * 10 + (size_t)b * 10;
#pragma unroll
        for (int j = 0; j < 10; j++) h[j] += p[j];
    }
#pragma unroll
    for (int j = 0; j < 10; j++) h[j] = fmaxf(h[j] + bfc[j], 0.f);
    float m = h[0];
#pragma unroll
    for (int j = 1; j < 10; j++) m = fmaxf(m, h[j]);
    float ex[10];
    float s = 0.f;
#pragma unroll
    for (int j = 0; j < 10; j++) { ex[j] = expf(h[j] - m); s += ex[j]; }
    float inv = 1.f / s;
#pragma unroll
    for (int j = 0; j < 10; j++) out[(size_t)b * 10 + j] = ex[j] * inv;
}

// ------------------------------- launch ----------------------------------
extern "C" void kernel_launch(void* const* d_in, const int* in_sizes, int n_in,
                              void* d_out, int out_size) {
    const float* x    = (const float*)d_in[0];
    const int*   rows = (const int*)d_in[1];
    const int*   cols = (const int*)d_in[2];
    const float* vals = (const float*)d_in[3];
    const float* Wgc  = (const float*)d_in[4];
    const float* bgc  = (const float*)d_in[5];
    const float* Wfc  = (const float*)d_in[6];
    const float* bfc  = (const float*)d_in[7];
    float* out = (float*)d_out;

    dim3 tb(32, 32), tg((NN + 31) / 32, (BB + 31) / 32);
    transpose_zero_kernel<<<tg, tb>>>(x);
    scatter_pad_kernel<<<(EE + 255) / 256, 256>>>(rows, cols, vals);
    pad_kernel<<<(NN * 32 + 255) / 256, 256>>>();

    // fused Chebyshev chain: all 19 steps in one persistent kernel
    cheb_kernel<<<NBLK, 256>>>();

    final_kernel<<<NCHUNK, 128>>>(Wgc, bgc, Wfc);
    reduce1_kernel<<<RCH, 128>>>();
    reduce_softmax_kernel<<<1, 128>>>(bfc, out);
}